// round 10
// baseline (speedup 1.0000x reference)
#include <cuda_runtime.h>

// Problem constants (fixed shapes from reference setup_inputs)
#define BATCH 4
#define NPTS  8192
#define CH    32      // input channels
#define KNN   16      // neighbors
#define LDIM  64      // hidden (dense)
#define ODIM  128     // output channels
#define TILE  128     // candidate tile (== TPB)
#define TPB   128     // threads per block = queries per block

// ---------------- device scratch (no allocs allowed) ----------------
__device__ float g_Wf[CH * ODIM];    // fused W_lin @ W_conv  [32,128]
__device__ float g_bf[ODIM];         // fused bias            [128]
__device__ float g_sq[BATCH * NPTS]; // per-point squared norms

// ---------------- packed f32x2 helpers ----------------
__device__ __forceinline__ void fma2(unsigned long long& acc,
                                     unsigned long long a,
                                     unsigned long long b) {
    asm("fma.rn.f32x2 %0, %1, %2, %3;" : "=l"(acc) : "l"(a), "l"(b), "l"(acc));
}
__device__ __forceinline__ float hsum2(unsigned long long v) {
    float lo, hi;
    asm("mov.b64 {%0, %1}, %2;" : "=f"(lo), "=f"(hi) : "l"(v));
    return lo + hi;
}

// ---------------- prep: fuse the two linear layers ----------------
// out = relu(pooled @ (W_lin@W_conv) + (b_lin@W_conv + b_conv))
__global__ void prep_weights(const float* __restrict__ W_lin,
                             const float* __restrict__ b_lin,
                             const float* __restrict__ W_conv,
                             const float* __restrict__ b_conv) {
    int o = threadIdx.x;             // 128 threads, one output channel each
    float bb = b_conv[o];
    for (int l = 0; l < LDIM; ++l) bb += b_lin[l] * W_conv[l * ODIM + o];
    g_bf[o] = bb;
    for (int c = 0; c < CH; ++c) {
        float acc = 0.f;
        for (int l = 0; l < LDIM; ++l)
            acc += W_lin[c * LDIM + l] * W_conv[l * ODIM + o];
        g_Wf[c * ODIM + o] = acc;
    }
}

// ---------------- prep: squared norms ----------------
__global__ void prep_sq(const float* __restrict__ x) {
    int p = blockIdx.x * blockDim.x + threadIdx.x;   // 0 .. BATCH*NPTS-1
    const float4* xp = reinterpret_cast<const float4*>(x + (size_t)p * CH);
    float s = 0.f;
#pragma unroll
    for (int i = 0; i < CH / 4; ++i) {
        float4 v = xp[i];
        s += v.x * v.x + v.y * v.y + v.z * v.z + v.w * v.w;
    }
    g_sq[p] = s;
}

// ---------------- main fused kernel ----------------
// One thread = one query point. Exact-fp32 KNN score: sq_j - 2*dot(x_i,x_j)
// (dropping the per-query constant sq_i keeps the ordering identical).
__global__ __launch_bounds__(TPB)
void knn_pool_mlp(const float* __restrict__ x, float* __restrict__ out) {
    __shared__ float4 s_cand[TILE * (CH / 4)];   // 16 KB candidate tile
    __shared__ float  s_sq[TILE];
    __shared__ float  s_Wf[CH * ODIM];           // 16 KB fused weights
    __shared__ float  s_bf[ODIM];

    const int blocks_per_batch = NPTS / TPB;     // 64
    const int b  = blockIdx.x / blocks_per_batch;
    const int q0 = (blockIdx.x % blocks_per_batch) * TPB;
    const int t  = threadIdx.x;
    const int q  = q0 + t;
    const float* xb = x + (size_t)b * NPTS * CH;

    // stage fused weights (once per block)
#pragma unroll
    for (int i = t; i < CH * ODIM; i += TPB) s_Wf[i] = g_Wf[i];
    s_bf[t] = g_bf[t];                            // ODIM == TPB

    // load query features as 16 packed f32x2 registers
    unsigned long long q2[CH / 2];
    {
        const ulonglong2* qp =
            reinterpret_cast<const ulonglong2*>(xb + (size_t)q * CH);
#pragma unroll
        for (int i = 0; i < CH / 4; ++i) {
            ulonglong2 v = qp[i];
            q2[2 * i]     = v.x;
            q2[2 * i + 1] = v.y;
        }
    }

    // top-16 smallest scores, sorted ascending, in registers
    float best_d[KNN];
    int   best_i[KNN];
#pragma unroll
    for (int r = 0; r < KNN; ++r) { best_d[r] = INFINITY; best_i[r] = -1; }
    float worst = INFINITY;

    const float* sqb = g_sq + b * NPTS;

    for (int j0 = 0; j0 < NPTS; j0 += TILE) {
        __syncthreads();   // previous tile fully consumed (also covers Wf load)
        {
            const float4* src =
                reinterpret_cast<const float4*>(xb + (size_t)j0 * CH);
#pragma unroll
            for (int i = 0; i < TILE * (CH / 4) / TPB; ++i)
                s_cand[t + i * TPB] = src[t + i * TPB];
            s_sq[t] = sqb[j0 + t];                // TILE == TPB
        }
        __syncthreads();

        for (int jj = 0; jj < TILE; ++jj) {
            const ulonglong2* cp =
                reinterpret_cast<const ulonglong2*>(&s_cand[jj * (CH / 4)]);
            unsigned long long a0 = 0ull, a1 = 0ull;   // packed (0,0)
#pragma unroll
            for (int i = 0; i < CH / 4; ++i) {
                ulonglong2 v = cp[i];                   // broadcast LDS.128
                fma2(a0, q2[2 * i],     v.x);
                fma2(a1, q2[2 * i + 1], v.y);
            }
            float dot   = hsum2(a0) + hsum2(a1);
            float score = fmaf(-2.f, dot, s_sq[jj]);

            if (score < worst) {                        // rare path (~1-2%)
                float d = score;
                int   id = j0 + jj;
#pragma unroll
                for (int r = 0; r < KNN; ++r) {
                    float od = best_d[r];
                    int   oi = best_i[r];
                    bool  sw = d < od;                  // strict: ties keep lower idx
                    best_d[r] = sw ? d  : od;
                    best_i[r] = sw ? id : oi;
                    d  = sw ? od : d;
                    id = sw ? oi : id;
                }
                worst = best_d[KNN - 1];
            }
        }
    }

    // gather neighbor features + max pool (L2-resident: 1 MB/batch)
    float pooled[CH];
#pragma unroll
    for (int c = 0; c < CH; ++c) pooled[c] = -INFINITY;
#pragma unroll
    for (int r = 0; r < KNN; ++r) {
        const float4* np =
            reinterpret_cast<const float4*>(xb + (size_t)best_i[r] * CH);
#pragma unroll
        for (int i = 0; i < CH / 4; ++i) {
            float4 v = __ldg(np + i);
            pooled[4 * i + 0] = fmaxf(pooled[4 * i + 0], v.x);
            pooled[4 * i + 1] = fmaxf(pooled[4 * i + 1], v.y);
            pooled[4 * i + 2] = fmaxf(pooled[4 * i + 2], v.z);
            pooled[4 * i + 3] = fmaxf(pooled[4 * i + 3], v.w);
        }
    }

    // fused MLP: out = relu(pooled @ Wf + bf), Wf broadcast from smem
    float* outp = out + ((size_t)b * NPTS + q) * ODIM;
#pragma unroll
    for (int o0 = 0; o0 < ODIM; o0 += 32) {
        float acc[32];
#pragma unroll
        for (int oi = 0; oi < 32; ++oi) acc[oi] = s_bf[o0 + oi];
#pragma unroll
        for (int c = 0; c < CH; ++c) {
            float p = pooled[c];
            const float4* wrow =
                reinterpret_cast<const float4*>(&s_Wf[c * ODIM + o0]);
#pragma unroll
            for (int i = 0; i < 8; ++i) {
                float4 w = wrow[i];
                acc[4 * i + 0] = fmaf(p, w.x, acc[4 * i + 0]);
                acc[4 * i + 1] = fmaf(p, w.y, acc[4 * i + 1]);
                acc[4 * i + 2] = fmaf(p, w.z, acc[4 * i + 2]);
                acc[4 * i + 3] = fmaf(p, w.w, acc[4 * i + 3]);
            }
        }
        float4* op = reinterpret_cast<float4*>(outp + o0);
#pragma unroll
        for (int i = 0; i < 8; ++i) {
            float4 v;
            v.x = fmaxf(acc[4 * i + 0], 0.f);
            v.y = fmaxf(acc[4 * i + 1], 0.f);
            v.z = fmaxf(acc[4 * i + 2], 0.f);
            v.w = fmaxf(acc[4 * i + 3], 0.f);
            op[i] = v;
        }
    }
}

extern "C" void kernel_launch(void* const* d_in, const int* in_sizes, int n_in,
                              void* d_out, int out_size) {
    const float* x      = (const float*)d_in[0];  // [B,N,C]
    const float* W_lin  = (const float*)d_in[1];  // [C,L]
    const float* b_lin  = (const float*)d_in[2];  // [L]
    const float* W_conv = (const float*)d_in[3];  // [L,O]
    const float* b_conv = (const float*)d_in[4];  // [O]
    float* out = (float*)d_out;                   // [B,N,O]

    (void)in_sizes; (void)n_in; (void)out_size;

    prep_weights<<<1, ODIM>>>(W_lin, b_lin, W_conv, b_conv);
    prep_sq<<<(BATCH * NPTS) / 256, 256>>>(x);
    knn_pool_mlp<<<BATCH * (NPTS / TPB), TPB>>>(x, out);
}

// round 11
// speedup vs baseline: 1.0067x; 1.0067x over previous
#include <cuda_runtime.h>

// Problem constants (fixed shapes from reference setup_inputs)
#define BATCH 4
#define NPTS  8192
#define CH    32      // input channels
#define KNN   16      // neighbors
#define LDIM  64      // hidden (dense)
#define ODIM  128     // output channels
#define TILE  128     // candidate tile (== TPB)
#define TPB   128     // threads per block = queries per block

// ---------------- device scratch (no allocs allowed) ----------------
__device__ float g_Wf[CH * ODIM];    // fused W_lin @ W_conv  [32,128]
__device__ float g_bf[ODIM];         // fused bias            [128]
__device__ float g_sq[BATCH * NPTS]; // per-point squared norms

// ---------------- packed f32x2 helpers ----------------
__device__ __forceinline__ void fma2(unsigned long long& acc,
                                     unsigned long long a,
                                     unsigned long long b) {
    asm("fma.rn.f32x2 %0, %1, %2, %3;" : "=l"(acc) : "l"(a), "l"(b), "l"(acc));
}
__device__ __forceinline__ float hsum2(unsigned long long v) {
    float lo, hi;
    asm("mov.b64 {%0, %1}, %2;" : "=f"(lo), "=f"(hi) : "l"(v));
    return lo + hi;
}

// ---------------- prep: fuse the two linear layers ----------------
// out = relu(pooled @ (W_lin@W_conv) + (b_lin@W_conv + b_conv))
__global__ void prep_weights(const float* __restrict__ W_lin,
                             const float* __restrict__ b_lin,
                             const float* __restrict__ W_conv,
                             const float* __restrict__ b_conv) {
    int o = threadIdx.x;             // 128 threads, one output channel each
    float bb = b_conv[o];
    for (int l = 0; l < LDIM; ++l) bb += b_lin[l] * W_conv[l * ODIM + o];
    g_bf[o] = bb;
    for (int c = 0; c < CH; ++c) {
        float acc = 0.f;
        for (int l = 0; l < LDIM; ++l)
            acc += W_lin[c * LDIM + l] * W_conv[l * ODIM + o];
        g_Wf[c * ODIM + o] = acc;
    }
}

// ---------------- prep: squared norms ----------------
__global__ void prep_sq(const float* __restrict__ x) {
    int p = blockIdx.x * blockDim.x + threadIdx.x;   // 0 .. BATCH*NPTS-1
    const float4* xp = reinterpret_cast<const float4*>(x + (size_t)p * CH);
    float s = 0.f;
#pragma unroll
    for (int i = 0; i < CH / 4; ++i) {
        float4 v = xp[i];
        s += v.x * v.x + v.y * v.y + v.z * v.z + v.w * v.w;
    }
    g_sq[p] = s;
}

// ---------------- main fused kernel ----------------
// One thread = one query point. Exact-fp32 KNN score: sq_j - 2*dot(x_i,x_j)
// (dropping the per-query constant sq_i keeps the ordering identical).
__global__ __launch_bounds__(TPB)
void knn_pool_mlp(const float* __restrict__ x, float* __restrict__ out) {
    __shared__ float4 s_cand[TILE * (CH / 4)];   // 16 KB candidate tile
    __shared__ float  s_sq[TILE];
    __shared__ float  s_Wf[CH * ODIM];           // 16 KB fused weights
    __shared__ float  s_bf[ODIM];

    const int blocks_per_batch = NPTS / TPB;     // 64
    const int b  = blockIdx.x / blocks_per_batch;
    const int q0 = (blockIdx.x % blocks_per_batch) * TPB;
    const int t  = threadIdx.x;
    const int q  = q0 + t;
    const float* xb = x + (size_t)b * NPTS * CH;

    // stage fused weights (once per block)
#pragma unroll
    for (int i = t; i < CH * ODIM; i += TPB) s_Wf[i] = g_Wf[i];
    s_bf[t] = g_bf[t];                            // ODIM == TPB

    // load query features as 16 packed f32x2 registers
    unsigned long long q2[CH / 2];
    {
        const ulonglong2* qp =
            reinterpret_cast<const ulonglong2*>(xb + (size_t)q * CH);
#pragma unroll
        for (int i = 0; i < CH / 4; ++i) {
            ulonglong2 v = qp[i];
            q2[2 * i]     = v.x;
            q2[2 * i + 1] = v.y;
        }
    }

    // top-16 smallest scores, sorted ascending, in registers
    float best_d[KNN];
    int   best_i[KNN];
#pragma unroll
    for (int r = 0; r < KNN; ++r) { best_d[r] = INFINITY; best_i[r] = -1; }
    float worst = INFINITY;

    const float* sqb = g_sq + b * NPTS;

    for (int j0 = 0; j0 < NPTS; j0 += TILE) {
        __syncthreads();   // previous tile fully consumed (also covers Wf load)
        {
            const float4* src =
                reinterpret_cast<const float4*>(xb + (size_t)j0 * CH);
#pragma unroll
            for (int i = 0; i < TILE * (CH / 4) / TPB; ++i)
                s_cand[t + i * TPB] = src[t + i * TPB];
            s_sq[t] = sqb[j0 + t];                // TILE == TPB
        }
        __syncthreads();

        for (int jj = 0; jj < TILE; ++jj) {
            const ulonglong2* cp =
                reinterpret_cast<const ulonglong2*>(&s_cand[jj * (CH / 4)]);
            unsigned long long a0 = 0ull, a1 = 0ull;   // packed (0,0)
#pragma unroll
            for (int i = 0; i < CH / 4; ++i) {
                ulonglong2 v = cp[i];                   // broadcast LDS.128
                fma2(a0, q2[2 * i],     v.x);
                fma2(a1, q2[2 * i + 1], v.y);
            }
            float dot   = hsum2(a0) + hsum2(a1);
            float score = fmaf(-2.f, dot, s_sq[jj]);

            if (score < worst) {                        // rare path (~1-2%)
                float d = score;
                int   id = j0 + jj;
#pragma unroll
                for (int r = 0; r < KNN; ++r) {
                    float od = best_d[r];
                    int   oi = best_i[r];
                    bool  sw = d < od;                  // strict: ties keep lower idx
                    best_d[r] = sw ? d  : od;
                    best_i[r] = sw ? id : oi;
                    d  = sw ? od : d;
                    id = sw ? oi : id;
                }
                worst = best_d[KNN - 1];
            }
        }
    }

    // gather neighbor features + max pool (L2-resident: 1 MB/batch)
    float pooled[CH];
#pragma unroll
    for (int c = 0; c < CH; ++c) pooled[c] = -INFINITY;
#pragma unroll
    for (int r = 0; r < KNN; ++r) {
        const float4* np =
            reinterpret_cast<const float4*>(xb + (size_t)best_i[r] * CH);
#pragma unroll
        for (int i = 0; i < CH / 4; ++i) {
            float4 v = __ldg(np + i);
            pooled[4 * i + 0] = fmaxf(pooled[4 * i + 0], v.x);
            pooled[4 * i + 1] = fmaxf(pooled[4 * i + 1], v.y);
            pooled[4 * i + 2] = fmaxf(pooled[4 * i + 2], v.z);
            pooled[4 * i + 3] = fmaxf(pooled[4 * i + 3], v.w);
        }
    }

    // fused MLP: out = relu(pooled @ Wf + bf), Wf broadcast from smem
    float* outp = out + ((size_t)b * NPTS + q) * ODIM;
#pragma unroll
    for (int o0 = 0; o0 < ODIM; o0 += 32) {
        float acc[32];
#pragma unroll
        for (int oi = 0; oi < 32; ++oi) acc[oi] = s_bf[o0 + oi];
#pragma unroll
        for (int c = 0; c < CH; ++c) {
            float p = pooled[c];
            const float4* wrow =
                reinterpret_cast<const float4*>(&s_Wf[c * ODIM + o0]);
#pragma unroll
            for (int i = 0; i < 8; ++i) {
                float4 w = wrow[i];
                acc[4 * i + 0] = fmaf(p, w.x, acc[4 * i + 0]);
                acc[4 * i + 1] = fmaf(p, w.y, acc[4 * i + 1]);
                acc[4 * i + 2] = fmaf(p, w.z, acc[4 * i + 2]);
                acc[4 * i + 3] = fmaf(p, w.w, acc[4 * i + 3]);
            }
        }
        float4* op = reinterpret_cast<float4*>(outp + o0);
#pragma unroll
        for (int i = 0; i < 8; ++i) {
            float4 v;
            v.x = fmaxf(acc[4 * i + 0], 0.f);
            v.y = fmaxf(acc[4 * i + 1], 0.f);
            v.z = fmaxf(acc[4 * i + 2], 0.f);
            v.w = fmaxf(acc[4 * i + 3], 0.f);
            op[i] = v;
        }
    }
}

extern "C" void kernel_launch(void* const* d_in, const int* in_sizes, int n_in,
                              void* d_out, int out_size) {
    const float* x      = (const float*)d_in[0];  // [B,N,C]
    const float* W_lin  = (const float*)d_in[1];  // [C,L]
    const float* b_lin  = (const float*)d_in[2];  // [L]
    const float* W_conv = (const float*)d_in[3];  // [L,O]
    const float* b_conv = (const float*)d_in[4];  // [O]
    float* out = (float*)d_out;                   // [B,N,O]

    (void)in_sizes; (void)n_in; (void)out_size;

    prep_weights<<<1, ODIM>>>(W_lin, b_lin, W_conv, b_conv);
    prep_sq<<<(BATCH * NPTS) / 256, 256>>>(x);
    knn_pool_mlp<<<BATCH * (NPTS / TPB), TPB>>>(x, out);
}

// round 12
// speedup vs baseline: 1.0071x; 1.0004x over previous
#include <cuda_runtime.h>

// Problem constants (fixed shapes from reference setup_inputs)
#define BATCH 4
#define NPTS  8192
#define CH    32      // input channels
#define KNN   16      // neighbors
#define LDIM  64      // hidden (dense)
#define ODIM  128     // output channels
#define TILE  128     // candidate tile (== TPB)
#define TPB   128     // threads per block = queries per block

// ---------------- device scratch (no allocs allowed) ----------------
__device__ float g_Wf[CH * ODIM];    // fused W_lin @ W_conv  [32,128]
__device__ float g_bf[ODIM];         // fused bias            [128]
__device__ float g_sq[BATCH * NPTS]; // per-point squared norms

// ---------------- packed f32x2 helpers ----------------
__device__ __forceinline__ void fma2(unsigned long long& acc,
                                     unsigned long long a,
                                     unsigned long long b) {
    asm("fma.rn.f32x2 %0, %1, %2, %3;" : "=l"(acc) : "l"(a), "l"(b), "l"(acc));
}
__device__ __forceinline__ float hsum2(unsigned long long v) {
    float lo, hi;
    asm("mov.b64 {%0, %1}, %2;" : "=f"(lo), "=f"(hi) : "l"(v));
    return lo + hi;
}

// ---------------- prep: fuse the two linear layers ----------------
// out = relu(pooled @ (W_lin@W_conv) + (b_lin@W_conv + b_conv))
__global__ void prep_weights(const float* __restrict__ W_lin,
                             const float* __restrict__ b_lin,
                             const float* __restrict__ W_conv,
                             const float* __restrict__ b_conv) {
    int o = threadIdx.x;             // 128 threads, one output channel each
    float bb = b_conv[o];
    for (int l = 0; l < LDIM; ++l) bb += b_lin[l] * W_conv[l * ODIM + o];
    g_bf[o] = bb;
    for (int c = 0; c < CH; ++c) {
        float acc = 0.f;
        for (int l = 0; l < LDIM; ++l)
            acc += W_lin[c * LDIM + l] * W_conv[l * ODIM + o];
        g_Wf[c * ODIM + o] = acc;
    }
}

// ---------------- prep: squared norms ----------------
__global__ void prep_sq(const float* __restrict__ x) {
    int p = blockIdx.x * blockDim.x + threadIdx.x;   // 0 .. BATCH*NPTS-1
    const float4* xp = reinterpret_cast<const float4*>(x + (size_t)p * CH);
    float s = 0.f;
#pragma unroll
    for (int i = 0; i < CH / 4; ++i) {
        float4 v = xp[i];
        s += v.x * v.x + v.y * v.y + v.z * v.z + v.w * v.w;
    }
    g_sq[p] = s;
}

// ---------------- main fused kernel ----------------
// One thread = one query point. Exact-fp32 KNN score: sq_j - 2*dot(x_i,x_j)
// (dropping the per-query constant sq_i keeps the ordering identical).
__global__ __launch_bounds__(TPB)
void knn_pool_mlp(const float* __restrict__ x, float* __restrict__ out) {
    __shared__ float4 s_cand[TILE * (CH / 4)];   // 16 KB candidate tile
    __shared__ float  s_sq[TILE];
    __shared__ float  s_Wf[CH * ODIM];           // 16 KB fused weights
    __shared__ float  s_bf[ODIM];

    const int blocks_per_batch = NPTS / TPB;     // 64
    const int b  = blockIdx.x / blocks_per_batch;
    const int q0 = (blockIdx.x % blocks_per_batch) * TPB;
    const int t  = threadIdx.x;
    const int q  = q0 + t;
    const float* xb = x + (size_t)b * NPTS * CH;

    // stage fused weights (once per block)
#pragma unroll
    for (int i = t; i < CH * ODIM; i += TPB) s_Wf[i] = g_Wf[i];
    s_bf[t] = g_bf[t];                            // ODIM == TPB

    // load query features as 16 packed f32x2 registers
    unsigned long long q2[CH / 2];
    {
        const ulonglong2* qp =
            reinterpret_cast<const ulonglong2*>(xb + (size_t)q * CH);
#pragma unroll
        for (int i = 0; i < CH / 4; ++i) {
            ulonglong2 v = qp[i];
            q2[2 * i]     = v.x;
            q2[2 * i + 1] = v.y;
        }
    }

    // top-16 smallest scores, sorted ascending, in registers
    float best_d[KNN];
    int   best_i[KNN];
#pragma unroll
    for (int r = 0; r < KNN; ++r) { best_d[r] = INFINITY; best_i[r] = -1; }
    float worst = INFINITY;

    const float* sqb = g_sq + b * NPTS;

    for (int j0 = 0; j0 < NPTS; j0 += TILE) {
        __syncthreads();   // previous tile fully consumed (also covers Wf load)
        {
            const float4* src =
                reinterpret_cast<const float4*>(xb + (size_t)j0 * CH);
#pragma unroll
            for (int i = 0; i < TILE * (CH / 4) / TPB; ++i)
                s_cand[t + i * TPB] = src[t + i * TPB];
            s_sq[t] = sqb[j0 + t];                // TILE == TPB
        }
        __syncthreads();

        for (int jj = 0; jj < TILE; ++jj) {
            const ulonglong2* cp =
                reinterpret_cast<const ulonglong2*>(&s_cand[jj * (CH / 4)]);
            unsigned long long a0 = 0ull, a1 = 0ull;   // packed (0,0)
#pragma unroll
            for (int i = 0; i < CH / 4; ++i) {
                ulonglong2 v = cp[i];                   // broadcast LDS.128
                fma2(a0, q2[2 * i],     v.x);
                fma2(a1, q2[2 * i + 1], v.y);
            }
            float dot   = hsum2(a0) + hsum2(a1);
            float score = fmaf(-2.f, dot, s_sq[jj]);

            if (score < worst) {                        // rare path (~1-2%)
                float d = score;
                int   id = j0 + jj;
#pragma unroll
                for (int r = 0; r < KNN; ++r) {
                    float od = best_d[r];
                    int   oi = best_i[r];
                    bool  sw = d < od;                  // strict: ties keep lower idx
                    best_d[r] = sw ? d  : od;
                    best_i[r] = sw ? id : oi;
                    d  = sw ? od : d;
                    id = sw ? oi : id;
                }
                worst = best_d[KNN - 1];
            }
        }
    }

    // gather neighbor features + max pool (L2-resident: 1 MB/batch)
    float pooled[CH];
#pragma unroll
    for (int c = 0; c < CH; ++c) pooled[c] = -INFINITY;
#pragma unroll
    for (int r = 0; r < KNN; ++r) {
        const float4* np =
            reinterpret_cast<const float4*>(xb + (size_t)best_i[r] * CH);
#pragma unroll
        for (int i = 0; i < CH / 4; ++i) {
            float4 v = __ldg(np + i);
            pooled[4 * i + 0] = fmaxf(pooled[4 * i + 0], v.x);
            pooled[4 * i + 1] = fmaxf(pooled[4 * i + 1], v.y);
            pooled[4 * i + 2] = fmaxf(pooled[4 * i + 2], v.z);
            pooled[4 * i + 3] = fmaxf(pooled[4 * i + 3], v.w);
        }
    }

    // fused MLP: out = relu(pooled @ Wf + bf), Wf broadcast from smem
    float* outp = out + ((size_t)b * NPTS + q) * ODIM;
#pragma unroll
    for (int o0 = 0; o0 < ODIM; o0 += 32) {
        float acc[32];
#pragma unroll
        for (int oi = 0; oi < 32; ++oi) acc[oi] = s_bf[o0 + oi];
#pragma unroll
        for (int c = 0; c < CH; ++c) {
            float p = pooled[c];
            const float4* wrow =
                reinterpret_cast<const float4*>(&s_Wf[c * ODIM + o0]);
#pragma unroll
            for (int i = 0; i < 8; ++i) {
                float4 w = wrow[i];
                acc[4 * i + 0] = fmaf(p, w.x, acc[4 * i + 0]);
                acc[4 * i + 1] = fmaf(p, w.y, acc[4 * i + 1]);
                acc[4 * i + 2] = fmaf(p, w.z, acc[4 * i + 2]);
                acc[4 * i + 3] = fmaf(p, w.w, acc[4 * i + 3]);
            }
        }
        float4* op = reinterpret_cast<float4*>(outp + o0);
#pragma unroll
        for (int i = 0; i < 8; ++i) {
            float4 v;
            v.x = fmaxf(acc[4 * i + 0], 0.f);
            v.y = fmaxf(acc[4 * i + 1], 0.f);
            v.z = fmaxf(acc[4 * i + 2], 0.f);
            v.w = fmaxf(acc[4 * i + 3], 0.f);
            op[i] = v;
        }
    }
}

extern "C" void kernel_launch(void* const* d_in, const int* in_sizes, int n_in,
                              void* d_out, int out_size) {
    const float* x      = (const float*)d_in[0];  // [B,N,C]
    const float* W_lin  = (const float*)d_in[1];  // [C,L]
    const float* b_lin  = (const float*)d_in[2];  // [L]
    const float* W_conv = (const float*)d_in[3];  // [L,O]
    const float* b_conv = (const float*)d_in[4];  // [O]
    float* out = (float*)d_out;                   // [B,N,O]

    (void)in_sizes; (void)n_in; (void)out_size;

    prep_weights<<<1, ODIM>>>(W_lin, b_lin, W_conv, b_conv);
    prep_sq<<<(BATCH * NPTS) / 256, 256>>>(x);
    knn_pool_mlp<<<BATCH * (NPTS / TPB), TPB>>>(x, out);
}

// round 13
// speedup vs baseline: 1.0074x; 1.0003x over previous
#include <cuda_runtime.h>

// Problem constants (fixed shapes from reference setup_inputs)
#define BATCH 4
#define NPTS  8192
#define CH    32      // input channels
#define KNN   16      // neighbors
#define LDIM  64      // hidden (dense)
#define ODIM  128     // output channels
#define TILE  128     // candidate tile (== TPB)
#define TPB   128     // threads per block = queries per block

// ---------------- device scratch (no allocs allowed) ----------------
__device__ float g_Wf[CH * ODIM];    // fused W_lin @ W_conv  [32,128]
__device__ float g_bf[ODIM];         // fused bias            [128]
__device__ float g_sq[BATCH * NPTS]; // per-point squared norms

// ---------------- packed f32x2 helpers ----------------
__device__ __forceinline__ void fma2(unsigned long long& acc,
                                     unsigned long long a,
                                     unsigned long long b) {
    asm("fma.rn.f32x2 %0, %1, %2, %3;" : "=l"(acc) : "l"(a), "l"(b), "l"(acc));
}
__device__ __forceinline__ float hsum2(unsigned long long v) {
    float lo, hi;
    asm("mov.b64 {%0, %1}, %2;" : "=f"(lo), "=f"(hi) : "l"(v));
    return lo + hi;
}

// ---------------- prep: fuse the two linear layers ----------------
// out = relu(pooled @ (W_lin@W_conv) + (b_lin@W_conv + b_conv))
__global__ void prep_weights(const float* __restrict__ W_lin,
                             const float* __restrict__ b_lin,
                             const float* __restrict__ W_conv,
                             const float* __restrict__ b_conv) {
    int o = threadIdx.x;             // 128 threads, one output channel each
    float bb = b_conv[o];
    for (int l = 0; l < LDIM; ++l) bb += b_lin[l] * W_conv[l * ODIM + o];
    g_bf[o] = bb;
    for (int c = 0; c < CH; ++c) {
        float acc = 0.f;
        for (int l = 0; l < LDIM; ++l)
            acc += W_lin[c * LDIM + l] * W_conv[l * ODIM + o];
        g_Wf[c * ODIM + o] = acc;
    }
}

// ---------------- prep: squared norms ----------------
__global__ void prep_sq(const float* __restrict__ x) {
    int p = blockIdx.x * blockDim.x + threadIdx.x;   // 0 .. BATCH*NPTS-1
    const float4* xp = reinterpret_cast<const float4*>(x + (size_t)p * CH);
    float s = 0.f;
#pragma unroll
    for (int i = 0; i < CH / 4; ++i) {
        float4 v = xp[i];
        s += v.x * v.x + v.y * v.y + v.z * v.z + v.w * v.w;
    }
    g_sq[p] = s;
}

// ---------------- main fused kernel ----------------
// One thread = one query point. Exact-fp32 KNN score: sq_j - 2*dot(x_i,x_j)
// (dropping the per-query constant sq_i keeps the ordering identical).
__global__ __launch_bounds__(TPB)
void knn_pool_mlp(const float* __restrict__ x, float* __restrict__ out) {
    __shared__ float4 s_cand[TILE * (CH / 4)];   // 16 KB candidate tile
    __shared__ float  s_sq[TILE];
    __shared__ float  s_Wf[CH * ODIM];           // 16 KB fused weights
    __shared__ float  s_bf[ODIM];

    const int blocks_per_batch = NPTS / TPB;     // 64
    const int b  = blockIdx.x / blocks_per_batch;
    const int q0 = (blockIdx.x % blocks_per_batch) * TPB;
    const int t  = threadIdx.x;
    const int q  = q0 + t;
    const float* xb = x + (size_t)b * NPTS * CH;

    // stage fused weights (once per block)
#pragma unroll
    for (int i = t; i < CH * ODIM; i += TPB) s_Wf[i] = g_Wf[i];
    s_bf[t] = g_bf[t];                            // ODIM == TPB

    // load query features as 16 packed f32x2 registers
    unsigned long long q2[CH / 2];
    {
        const ulonglong2* qp =
            reinterpret_cast<const ulonglong2*>(xb + (size_t)q * CH);
#pragma unroll
        for (int i = 0; i < CH / 4; ++i) {
            ulonglong2 v = qp[i];
            q2[2 * i]     = v.x;
            q2[2 * i + 1] = v.y;
        }
    }

    // top-16 smallest scores, sorted ascending, in registers
    float best_d[KNN];
    int   best_i[KNN];
#pragma unroll
    for (int r = 0; r < KNN; ++r) { best_d[r] = INFINITY; best_i[r] = -1; }
    float worst = INFINITY;

    const float* sqb = g_sq + b * NPTS;

    for (int j0 = 0; j0 < NPTS; j0 += TILE) {
        __syncthreads();   // previous tile fully consumed (also covers Wf load)
        {
            const float4* src =
                reinterpret_cast<const float4*>(xb + (size_t)j0 * CH);
#pragma unroll
            for (int i = 0; i < TILE * (CH / 4) / TPB; ++i)
                s_cand[t + i * TPB] = src[t + i * TPB];
            s_sq[t] = sqb[j0 + t];                // TILE == TPB
        }
        __syncthreads();

        for (int jj = 0; jj < TILE; ++jj) {
            const ulonglong2* cp =
                reinterpret_cast<const ulonglong2*>(&s_cand[jj * (CH / 4)]);
            unsigned long long a0 = 0ull, a1 = 0ull;   // packed (0,0)
#pragma unroll
            for (int i = 0; i < CH / 4; ++i) {
                ulonglong2 v = cp[i];                   // broadcast LDS.128
                fma2(a0, q2[2 * i],     v.x);
                fma2(a1, q2[2 * i + 1], v.y);
            }
            float dot   = hsum2(a0) + hsum2(a1);
            float score = fmaf(-2.f, dot, s_sq[jj]);

            if (score < worst) {                        // rare path (~1-2%)
                float d = score;
                int   id = j0 + jj;
#pragma unroll
                for (int r = 0; r < KNN; ++r) {
                    float od = best_d[r];
                    int   oi = best_i[r];
                    bool  sw = d < od;                  // strict: ties keep lower idx
                    best_d[r] = sw ? d  : od;
                    best_i[r] = sw ? id : oi;
                    d  = sw ? od : d;
                    id = sw ? oi : id;
                }
                worst = best_d[KNN - 1];
            }
        }
    }

    // gather neighbor features + max pool (L2-resident: 1 MB/batch)
    float pooled[CH];
#pragma unroll
    for (int c = 0; c < CH; ++c) pooled[c] = -INFINITY;
#pragma unroll
    for (int r = 0; r < KNN; ++r) {
        const float4* np =
            reinterpret_cast<const float4*>(xb + (size_t)best_i[r] * CH);
#pragma unroll
        for (int i = 0; i < CH / 4; ++i) {
            float4 v = __ldg(np + i);
            pooled[4 * i + 0] = fmaxf(pooled[4 * i + 0], v.x);
            pooled[4 * i + 1] = fmaxf(pooled[4 * i + 1], v.y);
            pooled[4 * i + 2] = fmaxf(pooled[4 * i + 2], v.z);
            pooled[4 * i + 3] = fmaxf(pooled[4 * i + 3], v.w);
        }
    }

    // fused MLP: out = relu(pooled @ Wf + bf), Wf broadcast from smem
    float* outp = out + ((size_t)b * NPTS + q) * ODIM;
#pragma unroll
    for (int o0 = 0; o0 < ODIM; o0 += 32) {
        float acc[32];
#pragma unroll
        for (int oi = 0; oi < 32; ++oi) acc[oi] = s_bf[o0 + oi];
#pragma unroll
        for (int c = 0; c < CH; ++c) {
            float p = pooled[c];
            const float4* wrow =
                reinterpret_cast<const float4*>(&s_Wf[c * ODIM + o0]);
#pragma unroll
            for (int i = 0; i < 8; ++i) {
                float4 w = wrow[i];
                acc[4 * i + 0] = fmaf(p, w.x, acc[4 * i + 0]);
                acc[4 * i + 1] = fmaf(p, w.y, acc[4 * i + 1]);
                acc[4 * i + 2] = fmaf(p, w.z, acc[4 * i + 2]);
                acc[4 * i + 3] = fmaf(p, w.w, acc[4 * i + 3]);
            }
        }
        float4* op = reinterpret_cast<float4*>(outp + o0);
#pragma unroll
        for (int i = 0; i < 8; ++i) {
            float4 v;
            v.x = fmaxf(acc[4 * i + 0], 0.f);
            v.y = fmaxf(acc[4 * i + 1], 0.f);
            v.z = fmaxf(acc[4 * i + 2], 0.f);
            v.w = fmaxf(acc[4 * i + 3], 0.f);
            op[i] = v;
        }
    }
}

extern "C" void kernel_launch(void* const* d_in, const int* in_sizes, int n_in,
                              void* d_out, int out_size) {
    const float* x      = (const float*)d_in[0];  // [B,N,C]
    const float* W_lin  = (const float*)d_in[1];  // [C,L]
    const float* b_lin  = (const float*)d_in[2];  // [L]
    const float* W_conv = (const float*)d_in[3];  // [L,O]
    const float* b_conv = (const float*)d_in[4];  // [O]
    float* out = (float*)d_out;                   // [B,N,O]

    (void)in_sizes; (void)n_in; (void)out_size;

    prep_weights<<<1, ODIM>>>(W_lin, b_lin, W_conv, b_conv);
    prep_sq<<<(BATCH * NPTS) / 256, 256>>>(x);
    knn_pool_mlp<<<BATCH * (NPTS / TPB), TPB>>>(x, out);
}

// round 14
// speedup vs baseline: 1.2877x; 1.2782x over previous
#include <cuda_runtime.h>

// Problem constants (fixed shapes from reference setup_inputs)
#define BATCH 4
#define NPTS  8192
#define CH    32      // input channels
#define KNN   16      // neighbors
#define LDIM  64      // hidden (dense)
#define ODIM  128     // output channels
#define TILE  128     // candidate tile (== TPB)
#define TPB   128     // threads per block = queries per block
#define SPLIT 2       // candidate-range split (occupancy lever)
#define CSPAN (NPTS / SPLIT)   // candidates per phase-A block: 4096

// ---------------- device scratch (no allocs allowed) ----------------
__device__ float g_Wf[CH * ODIM];          // fused W_lin @ W_conv  [32,128]
__device__ float g_bf[ODIM];               // fused bias            [128]
__device__ float g_sq[BATCH * NPTS];       // per-point squared norms
__device__ float g_pd[BATCH * NPTS * SPLIT * KNN];  // partial top-16 dists (4 MB)
__device__ int   g_pi[BATCH * NPTS * SPLIT * KNN];  // partial top-16 idx   (4 MB)

// ---------------- packed f32x2 helpers ----------------
__device__ __forceinline__ void fma2(unsigned long long& acc,
                                     unsigned long long a,
                                     unsigned long long b) {
    asm("fma.rn.f32x2 %0, %1, %2, %3;" : "=l"(acc) : "l"(a), "l"(b), "l"(acc));
}
__device__ __forceinline__ float hsum2(unsigned long long v) {
    float lo, hi;
    asm("mov.b64 {%0, %1}, %2;" : "=f"(lo), "=f"(hi) : "l"(v));
    return lo + hi;
}

// ---------------- prep: fuse the two linear layers (parallel) ----------------
// out = relu(pooled @ (W_lin@W_conv) + (b_lin@W_conv + b_conv))
// grid = CH blocks (one input channel each), TPB = ODIM threads.
__global__ void prep_weights(const float* __restrict__ W_lin,
                             const float* __restrict__ b_lin,
                             const float* __restrict__ W_conv,
                             const float* __restrict__ b_conv) {
    __shared__ float s_wl[LDIM];
    const int c = blockIdx.x;
    const int o = threadIdx.x;
    if (o < LDIM) s_wl[o] = W_lin[c * LDIM + o];
    __syncthreads();
    float acc = 0.f;
#pragma unroll
    for (int l = 0; l < LDIM; ++l)
        acc = fmaf(s_wl[l], W_conv[l * ODIM + o], acc);
    g_Wf[c * ODIM + o] = acc;
    if (c == 0) {
        float bb = b_conv[o];
#pragma unroll
        for (int l = 0; l < LDIM; ++l)
            bb = fmaf(b_lin[l], W_conv[l * ODIM + o], bb);
        g_bf[o] = bb;
    }
}

// ---------------- prep: squared norms ----------------
__global__ void prep_sq(const float* __restrict__ x) {
    int p = blockIdx.x * blockDim.x + threadIdx.x;   // 0 .. BATCH*NPTS-1
    const float4* xp = reinterpret_cast<const float4*>(x + (size_t)p * CH);
    float s = 0.f;
#pragma unroll
    for (int i = 0; i < CH / 4; ++i) {
        float4 v = xp[i];
        s += v.x * v.x + v.y * v.y + v.z * v.z + v.w * v.w;
    }
    g_sq[p] = s;
}

// ---------------- phase A: partial KNN over half the candidates ----------------
// One thread = one query. Score: sq_j - 2*dot(x_i,x_j) (per-query constant
// sq_i dropped; ordering identical). Block covers candidates
// [s*CSPAN, (s+1)*CSPAN). Results: sorted-ascending top-16 per (query, half).
__global__ __launch_bounds__(TPB, 4)
void knn_partial(const float* __restrict__ x) {
    __shared__ float4 s_cand[TILE * (CH / 4)];   // 16 KB candidate tile
    __shared__ float  s_sq[TILE];

    const int blocks_per_batch = (NPTS / TPB) * SPLIT;   // 128
    const int b   = blockIdx.x / blocks_per_batch;
    const int rem = blockIdx.x % blocks_per_batch;
    const int q0  = (rem / SPLIT) * TPB;
    const int s   = rem % SPLIT;
    const int t   = threadIdx.x;
    const int q   = q0 + t;
    const int jbase = s * CSPAN;
    const float* xb = x + (size_t)b * NPTS * CH;

    // load query features as 16 packed f32x2 registers
    unsigned long long q2[CH / 2];
    {
        const ulonglong2* qp =
            reinterpret_cast<const ulonglong2*>(xb + (size_t)q * CH);
#pragma unroll
        for (int i = 0; i < CH / 4; ++i) {
            ulonglong2 v = qp[i];
            q2[2 * i]     = v.x;
            q2[2 * i + 1] = v.y;
        }
    }

    // top-16 smallest scores, sorted ascending, in registers
    float best_d[KNN];
    int   best_i[KNN];
#pragma unroll
    for (int r = 0; r < KNN; ++r) { best_d[r] = INFINITY; best_i[r] = -1; }
    float worst = INFINITY;

    const float* sqb = g_sq + b * NPTS;

    for (int j0 = jbase; j0 < jbase + CSPAN; j0 += TILE) {
        __syncthreads();   // previous tile fully consumed
        {
            const float4* src =
                reinterpret_cast<const float4*>(xb + (size_t)j0 * CH);
#pragma unroll
            for (int i = 0; i < TILE * (CH / 4) / TPB; ++i)
                s_cand[t + i * TPB] = src[t + i * TPB];
            s_sq[t] = sqb[j0 + t];                // TILE == TPB
        }
        __syncthreads();

        for (int jj = 0; jj < TILE; jj += 2) {
            const ulonglong2* cp0 =
                reinterpret_cast<const ulonglong2*>(&s_cand[jj * (CH / 4)]);
            const ulonglong2* cp1 =
                reinterpret_cast<const ulonglong2*>(&s_cand[(jj + 1) * (CH / 4)]);
            unsigned long long a0 = 0ull, a1 = 0ull;   // candidate jj
            unsigned long long c0 = 0ull, c1 = 0ull;   // candidate jj+1
#pragma unroll
            for (int i = 0; i < CH / 4; ++i) {
                ulonglong2 v0 = cp0[i];                 // broadcast LDS.128
                ulonglong2 v1 = cp1[i];
                fma2(a0, q2[2 * i],     v0.x);
                fma2(a1, q2[2 * i + 1], v0.y);
                fma2(c0, q2[2 * i],     v1.x);
                fma2(c1, q2[2 * i + 1], v1.y);
            }
            float score0 = fmaf(-2.f, hsum2(a0) + hsum2(a1), s_sq[jj]);
            float score1 = fmaf(-2.f, hsum2(c0) + hsum2(c1), s_sq[jj + 1]);

            if (score0 < worst) {
                float d = score0;
                int   id = j0 + jj;
#pragma unroll
                for (int r = 0; r < KNN; ++r) {
                    float od = best_d[r];
                    int   oi = best_i[r];
                    bool  sw = d < od;                  // strict: ties keep lower idx
                    best_d[r] = sw ? d  : od;
                    best_i[r] = sw ? id : oi;
                    d  = sw ? od : d;
                    id = sw ? oi : id;
                }
                worst = best_d[KNN - 1];
            }
            if (score1 < worst) {
                float d = score1;
                int   id = j0 + jj + 1;
#pragma unroll
                for (int r = 0; r < KNN; ++r) {
                    float od = best_d[r];
                    int   oi = best_i[r];
                    bool  sw = d < od;
                    best_d[r] = sw ? d  : od;
                    best_i[r] = sw ? id : oi;
                    d  = sw ? od : d;
                    id = sw ? oi : id;
                }
                worst = best_d[KNN - 1];
            }
        }
    }

    // write sorted partial result
    const size_t base = ((size_t)(b * NPTS + q) * SPLIT + s) * KNN;
    float4* pd = reinterpret_cast<float4*>(g_pd + base);
    int4*   pi = reinterpret_cast<int4*>(g_pi + base);
#pragma unroll
    for (int r = 0; r < KNN / 4; ++r) {
        pd[r] = make_float4(best_d[4 * r], best_d[4 * r + 1],
                            best_d[4 * r + 2], best_d[4 * r + 3]);
        pi[r] = make_int4(best_i[4 * r], best_i[4 * r + 1],
                          best_i[4 * r + 2], best_i[4 * r + 3]);
    }
}

// ---------------- phase B: merge halves + gather + max-pool + fused MLP ------
__global__ __launch_bounds__(TPB)
void merge_gather_mlp(const float* __restrict__ x, float* __restrict__ out) {
    __shared__ float s_Wf[CH * ODIM];            // 16 KB fused weights
    __shared__ float s_bf[ODIM];

    const int blocks_per_batch = NPTS / TPB;     // 64
    const int b  = blockIdx.x / blocks_per_batch;
    const int q0 = (blockIdx.x % blocks_per_batch) * TPB;
    const int t  = threadIdx.x;
    const int q  = q0 + t;
    const float* xb = x + (size_t)b * NPTS * CH;

#pragma unroll
    for (int i = t; i < CH * ODIM; i += TPB) s_Wf[i] = g_Wf[i];
    s_bf[t] = g_bf[t];                            // ODIM == TPB
    __syncthreads();

    // load half-A as the working sorted top-16
    const size_t baseA = (size_t)(b * NPTS + q) * SPLIT * KNN;
    float best_d[KNN];
    int   best_i[KNN];
    {
        const float4* pd = reinterpret_cast<const float4*>(g_pd + baseA);
        const int4*   pi = reinterpret_cast<const int4*>(g_pi + baseA);
#pragma unroll
        for (int r = 0; r < KNN / 4; ++r) {
            float4 d4 = pd[r];  int4 i4 = pi[r];
            best_d[4 * r] = d4.x; best_d[4 * r + 1] = d4.y;
            best_d[4 * r + 2] = d4.z; best_d[4 * r + 3] = d4.w;
            best_i[4 * r] = i4.x; best_i[4 * r + 1] = i4.y;
            best_i[4 * r + 2] = i4.z; best_i[4 * r + 3] = i4.w;
        }
    }
    float worst = best_d[KNN - 1];

    // insert half-B (all its indices are larger -> strict < keeps the
    // reference's lower-index tie preference)
    {
        const float4* pd = reinterpret_cast<const float4*>(g_pd + baseA + KNN);
        const int4*   pi = reinterpret_cast<const int4*>(g_pi + baseA + KNN);
#pragma unroll
        for (int r4 = 0; r4 < KNN / 4; ++r4) {
            float4 d4 = pd[r4];  int4 i4 = pi[r4];
            float dv[4] = {d4.x, d4.y, d4.z, d4.w};
            int   iv[4] = {i4.x, i4.y, i4.z, i4.w};
#pragma unroll
            for (int u = 0; u < 4; ++u) {
                if (dv[u] < worst) {
                    float d = dv[u];
                    int   id = iv[u];
#pragma unroll
                    for (int r = 0; r < KNN; ++r) {
                        float od = best_d[r];
                        int   oi = best_i[r];
                        bool  sw = d < od;
                        best_d[r] = sw ? d  : od;
                        best_i[r] = sw ? id : oi;
                        d  = sw ? od : d;
                        id = sw ? oi : id;
                    }
                    worst = best_d[KNN - 1];
                }
            }
        }
    }

    // gather neighbor features + max pool (L2-resident: 1 MB/batch)
    float pooled[CH];
#pragma unroll
    for (int c = 0; c < CH; ++c) pooled[c] = -INFINITY;
#pragma unroll
    for (int r = 0; r < KNN; ++r) {
        const float4* np =
            reinterpret_cast<const float4*>(xb + (size_t)best_i[r] * CH);
#pragma unroll
        for (int i = 0; i < CH / 4; ++i) {
            float4 v = __ldg(np + i);
            pooled[4 * i + 0] = fmaxf(pooled[4 * i + 0], v.x);
            pooled[4 * i + 1] = fmaxf(pooled[4 * i + 1], v.y);
            pooled[4 * i + 2] = fmaxf(pooled[4 * i + 2], v.z);
            pooled[4 * i + 3] = fmaxf(pooled[4 * i + 3], v.w);
        }
    }

    // fused MLP: out = relu(pooled @ Wf + bf), Wf broadcast from smem
    float* outp = out + ((size_t)b * NPTS + q) * ODIM;
#pragma unroll
    for (int o0 = 0; o0 < ODIM; o0 += 32) {
        float acc[32];
#pragma unroll
        for (int oi = 0; oi < 32; ++oi) acc[oi] = s_bf[o0 + oi];
#pragma unroll
        for (int c = 0; c < CH; ++c) {
            float p = pooled[c];
            const float4* wrow =
                reinterpret_cast<const float4*>(&s_Wf[c * ODIM + o0]);
#pragma unroll
            for (int i = 0; i < 8; ++i) {
                float4 w = wrow[i];
                acc[4 * i + 0] = fmaf(p, w.x, acc[4 * i + 0]);
                acc[4 * i + 1] = fmaf(p, w.y, acc[4 * i + 1]);
                acc[4 * i + 2] = fmaf(p, w.z, acc[4 * i + 2]);
                acc[4 * i + 3] = fmaf(p, w.w, acc[4 * i + 3]);
            }
        }
        float4* op = reinterpret_cast<float4*>(outp + o0);
#pragma unroll
        for (int i = 0; i < 8; ++i) {
            float4 v;
            v.x = fmaxf(acc[4 * i + 0], 0.f);
            v.y = fmaxf(acc[4 * i + 1], 0.f);
            v.z = fmaxf(acc[4 * i + 2], 0.f);
            v.w = fmaxf(acc[4 * i + 3], 0.f);
            op[i] = v;
        }
    }
}

extern "C" void kernel_launch(void* const* d_in, const int* in_sizes, int n_in,
                              void* d_out, int out_size) {
    const float* x      = (const float*)d_in[0];  // [B,N,C]
    const float* W_lin  = (const float*)d_in[1];  // [C,L]
    const float* b_lin  = (const float*)d_in[2];  // [L]
    const float* W_conv = (const float*)d_in[3];  // [L,O]
    const float* b_conv = (const float*)d_in[4];  // [O]
    float* out = (float*)d_out;                   // [B,N,O]

    (void)in_sizes; (void)n_in; (void)out_size;

    prep_weights<<<CH, ODIM>>>(W_lin, b_lin, W_conv, b_conv);
    prep_sq<<<(BATCH * NPTS) / 256, 256>>>(x);
    knn_partial<<<BATCH * (NPTS / TPB) * SPLIT, TPB>>>(x);
    merge_gather_mlp<<<BATCH * (NPTS / TPB), TPB>>>(x, out);
}

// round 15
// speedup vs baseline: 1.2881x; 1.0003x over previous
#include <cuda_runtime.h>

// Problem constants (fixed shapes from reference setup_inputs)
#define BATCH 4
#define NPTS  8192
#define CH    32      // input channels
#define KNN   16      // neighbors
#define LDIM  64      // hidden (dense)
#define ODIM  128     // output channels
#define TILE  128     // candidate tile (== TPB)
#define TPB   128     // threads per block = queries per block
#define SPLIT 2       // candidate-range split (occupancy lever)
#define CSPAN (NPTS / SPLIT)   // candidates per phase-A block: 4096

// ---------------- device scratch (no allocs allowed) ----------------
__device__ float g_Wf[CH * ODIM];          // fused W_lin @ W_conv  [32,128]
__device__ float g_bf[ODIM];               // fused bias            [128]
__device__ float g_sq[BATCH * NPTS];       // per-point squared norms
__device__ float g_pd[BATCH * NPTS * SPLIT * KNN];  // partial top-16 dists (4 MB)
__device__ int   g_pi[BATCH * NPTS * SPLIT * KNN];  // partial top-16 idx   (4 MB)

// ---------------- packed f32x2 helpers ----------------
__device__ __forceinline__ void fma2(unsigned long long& acc,
                                     unsigned long long a,
                                     unsigned long long b) {
    asm("fma.rn.f32x2 %0, %1, %2, %3;" : "=l"(acc) : "l"(a), "l"(b), "l"(acc));
}
__device__ __forceinline__ float hsum2(unsigned long long v) {
    float lo, hi;
    asm("mov.b64 {%0, %1}, %2;" : "=f"(lo), "=f"(hi) : "l"(v));
    return lo + hi;
}

// ---------------- prep: fuse the two linear layers (parallel) ----------------
// out = relu(pooled @ (W_lin@W_conv) + (b_lin@W_conv + b_conv))
// grid = CH blocks (one input channel each), TPB = ODIM threads.
__global__ void prep_weights(const float* __restrict__ W_lin,
                             const float* __restrict__ b_lin,
                             const float* __restrict__ W_conv,
                             const float* __restrict__ b_conv) {
    __shared__ float s_wl[LDIM];
    const int c = blockIdx.x;
    const int o = threadIdx.x;
    if (o < LDIM) s_wl[o] = W_lin[c * LDIM + o];
    __syncthreads();
    float acc = 0.f;
#pragma unroll
    for (int l = 0; l < LDIM; ++l)
        acc = fmaf(s_wl[l], W_conv[l * ODIM + o], acc);
    g_Wf[c * ODIM + o] = acc;
    if (c == 0) {
        float bb = b_conv[o];
#pragma unroll
        for (int l = 0; l < LDIM; ++l)
            bb = fmaf(b_lin[l], W_conv[l * ODIM + o], bb);
        g_bf[o] = bb;
    }
}

// ---------------- prep: squared norms ----------------
__global__ void prep_sq(const float* __restrict__ x) {
    int p = blockIdx.x * blockDim.x + threadIdx.x;   // 0 .. BATCH*NPTS-1
    const float4* xp = reinterpret_cast<const float4*>(x + (size_t)p * CH);
    float s = 0.f;
#pragma unroll
    for (int i = 0; i < CH / 4; ++i) {
        float4 v = xp[i];
        s += v.x * v.x + v.y * v.y + v.z * v.z + v.w * v.w;
    }
    g_sq[p] = s;
}

// ---------------- phase A: partial KNN over half the candidates ----------------
// One thread = one query. Score: sq_j - 2*dot(x_i,x_j) (per-query constant
// sq_i dropped; ordering identical). Block covers candidates
// [s*CSPAN, (s+1)*CSPAN). Results: sorted-ascending top-16 per (query, half).
__global__ __launch_bounds__(TPB, 4)
void knn_partial(const float* __restrict__ x) {
    __shared__ float4 s_cand[TILE * (CH / 4)];   // 16 KB candidate tile
    __shared__ float  s_sq[TILE];

    const int blocks_per_batch = (NPTS / TPB) * SPLIT;   // 128
    const int b   = blockIdx.x / blocks_per_batch;
    const int rem = blockIdx.x % blocks_per_batch;
    const int q0  = (rem / SPLIT) * TPB;
    const int s   = rem % SPLIT;
    const int t   = threadIdx.x;
    const int q   = q0 + t;
    const int jbase = s * CSPAN;
    const float* xb = x + (size_t)b * NPTS * CH;

    // load query features as 16 packed f32x2 registers
    unsigned long long q2[CH / 2];
    {
        const ulonglong2* qp =
            reinterpret_cast<const ulonglong2*>(xb + (size_t)q * CH);
#pragma unroll
        for (int i = 0; i < CH / 4; ++i) {
            ulonglong2 v = qp[i];
            q2[2 * i]     = v.x;
            q2[2 * i + 1] = v.y;
        }
    }

    // top-16 smallest scores, sorted ascending, in registers
    float best_d[KNN];
    int   best_i[KNN];
#pragma unroll
    for (int r = 0; r < KNN; ++r) { best_d[r] = INFINITY; best_i[r] = -1; }
    float worst = INFINITY;

    const float* sqb = g_sq + b * NPTS;

    for (int j0 = jbase; j0 < jbase + CSPAN; j0 += TILE) {
        __syncthreads();   // previous tile fully consumed
        {
            const float4* src =
                reinterpret_cast<const float4*>(xb + (size_t)j0 * CH);
#pragma unroll
            for (int i = 0; i < TILE * (CH / 4) / TPB; ++i)
                s_cand[t + i * TPB] = src[t + i * TPB];
            s_sq[t] = sqb[j0 + t];                // TILE == TPB
        }
        __syncthreads();

        for (int jj = 0; jj < TILE; jj += 2) {
            const ulonglong2* cp0 =
                reinterpret_cast<const ulonglong2*>(&s_cand[jj * (CH / 4)]);
            const ulonglong2* cp1 =
                reinterpret_cast<const ulonglong2*>(&s_cand[(jj + 1) * (CH / 4)]);
            unsigned long long a0 = 0ull, a1 = 0ull;   // candidate jj
            unsigned long long c0 = 0ull, c1 = 0ull;   // candidate jj+1
#pragma unroll
            for (int i = 0; i < CH / 4; ++i) {
                ulonglong2 v0 = cp0[i];                 // broadcast LDS.128
                ulonglong2 v1 = cp1[i];
                fma2(a0, q2[2 * i],     v0.x);
                fma2(a1, q2[2 * i + 1], v0.y);
                fma2(c0, q2[2 * i],     v1.x);
                fma2(c1, q2[2 * i + 1], v1.y);
            }
            float score0 = fmaf(-2.f, hsum2(a0) + hsum2(a1), s_sq[jj]);
            float score1 = fmaf(-2.f, hsum2(c0) + hsum2(c1), s_sq[jj + 1]);

            if (score0 < worst) {
                float d = score0;
                int   id = j0 + jj;
#pragma unroll
                for (int r = 0; r < KNN; ++r) {
                    float od = best_d[r];
                    int   oi = best_i[r];
                    bool  sw = d < od;                  // strict: ties keep lower idx
                    best_d[r] = sw ? d  : od;
                    best_i[r] = sw ? id : oi;
                    d  = sw ? od : d;
                    id = sw ? oi : id;
                }
                worst = best_d[KNN - 1];
            }
            if (score1 < worst) {
                float d = score1;
                int   id = j0 + jj + 1;
#pragma unroll
                for (int r = 0; r < KNN; ++r) {
                    float od = best_d[r];
                    int   oi = best_i[r];
                    bool  sw = d < od;
                    best_d[r] = sw ? d  : od;
                    best_i[r] = sw ? id : oi;
                    d  = sw ? od : d;
                    id = sw ? oi : id;
                }
                worst = best_d[KNN - 1];
            }
        }
    }

    // write sorted partial result
    const size_t base = ((size_t)(b * NPTS + q) * SPLIT + s) * KNN;
    float4* pd = reinterpret_cast<float4*>(g_pd + base);
    int4*   pi = reinterpret_cast<int4*>(g_pi + base);
#pragma unroll
    for (int r = 0; r < KNN / 4; ++r) {
        pd[r] = make_float4(best_d[4 * r], best_d[4 * r + 1],
                            best_d[4 * r + 2], best_d[4 * r + 3]);
        pi[r] = make_int4(best_i[4 * r], best_i[4 * r + 1],
                          best_i[4 * r + 2], best_i[4 * r + 3]);
    }
}

// ---------------- phase B: merge halves + gather + max-pool + fused MLP ------
__global__ __launch_bounds__(TPB)
void merge_gather_mlp(const float* __restrict__ x, float* __restrict__ out) {
    __shared__ float s_Wf[CH * ODIM];            // 16 KB fused weights
    __shared__ float s_bf[ODIM];

    const int blocks_per_batch = NPTS / TPB;     // 64
    const int b  = blockIdx.x / blocks_per_batch;
    const int q0 = (blockIdx.x % blocks_per_batch) * TPB;
    const int t  = threadIdx.x;
    const int q  = q0 + t;
    const float* xb = x + (size_t)b * NPTS * CH;

#pragma unroll
    for (int i = t; i < CH * ODIM; i += TPB) s_Wf[i] = g_Wf[i];
    s_bf[t] = g_bf[t];                            // ODIM == TPB
    __syncthreads();

    // load half-A as the working sorted top-16
    const size_t baseA = (size_t)(b * NPTS + q) * SPLIT * KNN;
    float best_d[KNN];
    int   best_i[KNN];
    {
        const float4* pd = reinterpret_cast<const float4*>(g_pd + baseA);
        const int4*   pi = reinterpret_cast<const int4*>(g_pi + baseA);
#pragma unroll
        for (int r = 0; r < KNN / 4; ++r) {
            float4 d4 = pd[r];  int4 i4 = pi[r];
            best_d[4 * r] = d4.x; best_d[4 * r + 1] = d4.y;
            best_d[4 * r + 2] = d4.z; best_d[4 * r + 3] = d4.w;
            best_i[4 * r] = i4.x; best_i[4 * r + 1] = i4.y;
            best_i[4 * r + 2] = i4.z; best_i[4 * r + 3] = i4.w;
        }
    }
    float worst = best_d[KNN - 1];

    // insert half-B (all its indices are larger -> strict < keeps the
    // reference's lower-index tie preference)
    {
        const float4* pd = reinterpret_cast<const float4*>(g_pd + baseA + KNN);
        const int4*   pi = reinterpret_cast<const int4*>(g_pi + baseA + KNN);
#pragma unroll
        for (int r4 = 0; r4 < KNN / 4; ++r4) {
            float4 d4 = pd[r4];  int4 i4 = pi[r4];
            float dv[4] = {d4.x, d4.y, d4.z, d4.w};
            int   iv[4] = {i4.x, i4.y, i4.z, i4.w};
#pragma unroll
            for (int u = 0; u < 4; ++u) {
                if (dv[u] < worst) {
                    float d = dv[u];
                    int   id = iv[u];
#pragma unroll
                    for (int r = 0; r < KNN; ++r) {
                        float od = best_d[r];
                        int   oi = best_i[r];
                        bool  sw = d < od;
                        best_d[r] = sw ? d  : od;
                        best_i[r] = sw ? id : oi;
                        d  = sw ? od : d;
                        id = sw ? oi : id;
                    }
                    worst = best_d[KNN - 1];
                }
            }
        }
    }

    // gather neighbor features + max pool (L2-resident: 1 MB/batch)
    float pooled[CH];
#pragma unroll
    for (int c = 0; c < CH; ++c) pooled[c] = -INFINITY;
#pragma unroll
    for (int r = 0; r < KNN; ++r) {
        const float4* np =
            reinterpret_cast<const float4*>(xb + (size_t)best_i[r] * CH);
#pragma unroll
        for (int i = 0; i < CH / 4; ++i) {
            float4 v = __ldg(np + i);
            pooled[4 * i + 0] = fmaxf(pooled[4 * i + 0], v.x);
            pooled[4 * i + 1] = fmaxf(pooled[4 * i + 1], v.y);
            pooled[4 * i + 2] = fmaxf(pooled[4 * i + 2], v.z);
            pooled[4 * i + 3] = fmaxf(pooled[4 * i + 3], v.w);
        }
    }

    // fused MLP: out = relu(pooled @ Wf + bf), Wf broadcast from smem
    float* outp = out + ((size_t)b * NPTS + q) * ODIM;
#pragma unroll
    for (int o0 = 0; o0 < ODIM; o0 += 32) {
        float acc[32];
#pragma unroll
        for (int oi = 0; oi < 32; ++oi) acc[oi] = s_bf[o0 + oi];
#pragma unroll
        for (int c = 0; c < CH; ++c) {
            float p = pooled[c];
            const float4* wrow =
                reinterpret_cast<const float4*>(&s_Wf[c * ODIM + o0]);
#pragma unroll
            for (int i = 0; i < 8; ++i) {
                float4 w = wrow[i];
                acc[4 * i + 0] = fmaf(p, w.x, acc[4 * i + 0]);
                acc[4 * i + 1] = fmaf(p, w.y, acc[4 * i + 1]);
                acc[4 * i + 2] = fmaf(p, w.z, acc[4 * i + 2]);
                acc[4 * i + 3] = fmaf(p, w.w, acc[4 * i + 3]);
            }
        }
        float4* op = reinterpret_cast<float4*>(outp + o0);
#pragma unroll
        for (int i = 0; i < 8; ++i) {
            float4 v;
            v.x = fmaxf(acc[4 * i + 0], 0.f);
            v.y = fmaxf(acc[4 * i + 1], 0.f);
            v.z = fmaxf(acc[4 * i + 2], 0.f);
            v.w = fmaxf(acc[4 * i + 3], 0.f);
            op[i] = v;
        }
    }
}

extern "C" void kernel_launch(void* const* d_in, const int* in_sizes, int n_in,
                              void* d_out, int out_size) {
    const float* x      = (const float*)d_in[0];  // [B,N,C]
    const float* W_lin  = (const float*)d_in[1];  // [C,L]
    const float* b_lin  = (const float*)d_in[2];  // [L]
    const float* W_conv = (const float*)d_in[3];  // [L,O]
    const float* b_conv = (const float*)d_in[4];  // [O]
    float* out = (float*)d_out;                   // [B,N,O]

    (void)in_sizes; (void)n_in; (void)out_size;

    prep_weights<<<CH, ODIM>>>(W_lin, b_lin, W_conv, b_conv);
    prep_sq<<<(BATCH * NPTS) / 256, 256>>>(x);
    knn_partial<<<BATCH * (NPTS / TPB) * SPLIT, TPB>>>(x);
    merge_gather_mlp<<<BATCH * (NPTS / TPB), TPB>>>(x, out);
}